// round 11
// baseline (speedup 1.0000x reference)
#include <cuda_runtime.h>
#include <cuda_bf16.h>
#include <mma.h>
#include <cstdint>

using namespace nvcuda;

// Problem constants (fixed by the dataset)
#define MAXN 50000
#define MAXE 400000
#define HD 256          // H * D
#define D_DIM 128
#define NEG_SLOPE 0.2f

// ---------------- scratch (no allocations allowed) ----------------
__device__ float g_xl[(size_t)MAXN * HD];      // source projection  [N,256]
__device__ float g_xr[(size_t)MAXN * HD];      // target projection  [N,256]
__device__ float g_numer[(size_t)MAXN * HD];   // weighted sums (un-normalized)
__device__ float g_denom[(size_t)MAXN * 2];    // sum of exp(score) per node/head
__device__ float g_xt[(size_t)MAXN * D_DIM];   // x pre-rounded to tf32
__device__ float g_wt[3 * HD * D_DIM];         // Wl, Wr, Wo pre-rounded to tf32

__device__ __forceinline__ void red_add_v4(float* p, float a, float b, float c, float d) {
    asm volatile("red.global.add.v4.f32 [%0], {%1,%2,%3,%4};"
                 :: "l"(p), "f"(a), "f"(b), "f"(c), "f"(d) : "memory");
}
__device__ __forceinline__ void cp_async16(uint32_t saddr, const void* g, int szok) {
    asm volatile("cp.async.ca.shared.global [%0], [%1], 16, %2;"
                 :: "r"(saddr), "l"(g), "r"(szok) : "memory");
}
__device__ __forceinline__ float4 tf32_round4(float4 v) {
    v.x = wmma::__float_to_tf32(v.x); v.y = wmma::__float_to_tf32(v.y);
    v.z = wmma::__float_to_tf32(v.z); v.w = wmma::__float_to_tf32(v.w);
    return v;
}

// ---------------- init: zero numer/denom + pre-round x, Wl, Wr, Wo to tf32 ----------------
// float4 index space: [0, N*64)          -> zero numer
//                     [N*64, N*96)       -> convert x  -> g_xt
//                     [N*96, N*96+24576) -> convert Wl|Wr|Wo -> g_wt
__global__ void init_kernel(const float* __restrict__ x,
                            const float* __restrict__ Wl,
                            const float* __restrict__ Wr,
                            const float* __restrict__ Wo, int n_nodes) {
    int i = blockIdx.x * blockDim.x + threadIdx.x;
    int t0 = n_nodes * 64;
    int t1 = t0 + n_nodes * 32;
    if (i < t0) {
        ((float4*)g_numer)[i] = make_float4(0.f, 0.f, 0.f, 0.f);
    } else if (i < t1) {
        int j = i - t0;
        ((float4*)g_xt)[j] = tf32_round4(((const float4*)x)[j]);
    } else if (i < t1 + 24576) {
        int j = i - t1;                      // 0..24575 float4 = 3 x 8192
        const float4* src = (j < 8192) ? (const float4*)Wl
                          : (j < 16384) ? (const float4*)Wr - 8192
                          : (const float4*)Wo - 16384;
        ((float4*)g_wt)[j] = tf32_round4(src[j]);
    }
    if (i < n_nodes * 2) g_denom[i] = 0.f;
}

// ---------------- tf32 tensor-core GEMM, cp.async double-buffered ----------------
// mode 0: fused projections. A = g_xt [M,128] (pre-rounded), grid.x = 4:
//         bn<256 -> Wl/bl -> g_xl col (bn&255);  bn>=256 -> Wr/br -> g_xr col (bn&255)
// mode 1: final projection. A = g_numer [M,256] normalized+rounded on load,
//         W = g_wt+65536 (Wo), bias = biasa (=bo), C = Cparam [M,128]
#define BM 128
#define BN 128
#define BK 16
#define BKP 20          // padded smem stride (floats); 20*4=80B, 16B-aligned rows

__global__ __launch_bounds__(256, 2) void gemm_tf32(
    const float* __restrict__ biasa, const float* __restrict__ biasb,
    const float* __restrict__ bias_conv,
    float* __restrict__ Cparam, int mode, int M, int K)
{
    __shared__ float As[2][BM][BKP];
    __shared__ float Bs[2][BM][BKP];

    int tid  = threadIdx.x;
    int wid  = tid >> 5;
    int lane = tid & 31;
    int bm = blockIdx.y * BM;
    int bn = blockIdx.x * BN;

    const float* A;
    const float* W;
    const float* bias;
    float* C;
    int Ncol, cbase;
    if (mode == 0) {
        A = g_xt;
        bool second = bn >= 256;
        int wrow = bn & 255;
        W    = g_wt + (second ? (HD * D_DIM) : 0) + (size_t)wrow * K;
        bias = (second ? biasb : biasa) + wrow;
        C    = second ? g_xr : g_xl;
        Ncol = HD; cbase = wrow;
    } else {
        A = g_numer;
        W = g_wt + 2 * HD * D_DIM;
        bias = biasa;
        C = Cparam; Ncol = D_DIM; cbase = 0;
    }

    // warp tiling: 2 warps along M (64 rows), 4 along N (32 cols)
    int wm = (wid & 1) * 64;
    int wn = (wid >> 1) * 32;

    // ---- bias -> accumulator init (staged in As[0] region) ----
    float* bias_s = &As[0][0][0];               // 16 x 128 row-replicated (8KB <= 10.2KB)
    for (int i = tid; i < 16 * BN; i += 256) bias_s[i] = bias[i & 127];
    __syncthreads();

    wmma::fragment<wmma::accumulator, 16, 16, 8, float> acc[4][2];
#pragma unroll
    for (int i = 0; i < 4; i++)
#pragma unroll
        for (int j = 0; j < 2; j++)
            wmma::load_matrix_sync(acc[i][j], bias_s + wn + j * 16, BN, wmma::mem_row_major);
    __syncthreads();

    uint32_t as_base = (uint32_t)__cvta_generic_to_shared(&As[0][0][0]);
    uint32_t bs_base = (uint32_t)__cvta_generic_to_shared(&Bs[0][0][0]);

    auto load_tile = [&](int buf, int k0) {
        int head = (k0 >= D_DIM) ? 1 : 0;       // used only in mode 1
#pragma unroll
        for (int it = 0; it < 2; it++) {
            int idx  = tid + it * 256;           // 0..511
            int row  = idx >> 2;
            int col4 = (idx & 3) << 2;
            int grow = bm + row;
            uint32_t soff = ((uint32_t)(buf * BM + row) * BKP + col4) * 4;
            if (mode == 0) {
                const float* src = A + (size_t)(grow < M ? grow : 0) * K + k0 + col4;
                cp_async16(as_base + soff, src, grow < M ? 16 : 0);
            } else {
                float4 v = make_float4(0.f, 0.f, 0.f, 0.f);
                if (grow < M) {
                    v = *(const float4*)(A + (size_t)grow * K + k0 + col4);
                    float inv = 1.0f / (g_denom[(size_t)grow * 2 + head] + 1e-16f);
                    float4 bc = *(const float4*)(bias_conv + k0 + col4);
                    v.x = v.x * inv + bc.x; v.y = v.y * inv + bc.y;
                    v.z = v.z * inv + bc.z; v.w = v.w * inv + bc.w;
                    v = tf32_round4(v);
                }
                *(float4*)&As[buf][row][col4] = v;
            }
            const float* wsrc = W + (size_t)row * K + k0 + col4;
            cp_async16(bs_base + soff, wsrc, 16);
        }
    };

    int T = K / BK;
    load_tile(0, 0);
    asm volatile("cp.async.commit_group;");

    for (int t = 0; t < T; t++) {
        int buf = t & 1;
        if (t + 1 < T) {
            load_tile(buf ^ 1, (t + 1) * BK);
            asm volatile("cp.async.commit_group;");
            asm volatile("cp.async.wait_group 1;");
        } else {
            asm volatile("cp.async.wait_group 0;");
        }
        __syncthreads();

#pragma unroll
        for (int kk = 0; kk < BK; kk += 8) {
            wmma::fragment<wmma::matrix_a, 16, 16, 8, wmma::precision::tf32, wmma::row_major> af[4];
            wmma::fragment<wmma::matrix_b, 16, 16, 8, wmma::precision::tf32, wmma::col_major> bf[2];
#pragma unroll
            for (int i = 0; i < 4; i++)
                wmma::load_matrix_sync(af[i], &As[buf][wm + i * 16][kk], BKP);
#pragma unroll
            for (int j = 0; j < 2; j++)
                wmma::load_matrix_sync(bf[j], &Bs[buf][wn + j * 16][kk], BKP);
#pragma unroll
            for (int i = 0; i < 4; i++)
#pragma unroll
                for (int j = 0; j < 2; j++)
                    wmma::mma_sync(acc[i][j], af[i], bf[j], acc[i][j]);
        }
        __syncthreads();
    }

    // epilogue
    if (bm + BM <= M) {
#pragma unroll
        for (int i = 0; i < 4; i++)
#pragma unroll
            for (int j = 0; j < 2; j++)
                wmma::store_matrix_sync(C + (size_t)(bm + wm + i * 16) * Ncol + cbase + wn + j * 16,
                                        acc[i][j], Ncol, wmma::mem_row_major);
    } else {
        // remainder block: stage each 16x16 fragment in per-warp smem, guarded writes
        float* sw = &As[0][0][0] + wid * (16 * 20);
#pragma unroll
        for (int i = 0; i < 4; i++)
#pragma unroll
            for (int j = 0; j < 2; j++) {
                wmma::store_matrix_sync(sw, acc[i][j], 20, wmma::mem_row_major);
                __syncwarp();
                int r  = lane >> 1;
                int c0 = (lane & 1) * 8;
                int grow = bm + wm + i * 16 + r;
                if (grow < M) {
                    float* dst = C + (size_t)grow * Ncol + cbase + wn + j * 16 + c0;
#pragma unroll
                    for (int c = 0; c < 8; c++) dst[c] = sw[r * 20 + c0 + c];
                }
                __syncwarp();
            }
    }
}

// ---------------- edge pass, one head per launch, 2 edges per warp ----------------
// Working set per pass: xl/xr/numer half-slices = 77MB -> L2-resident.
__global__ __launch_bounds__(256) void edge_head_kernel(
    const int* __restrict__ ei, const float* __restrict__ att,
    int E, int n_nodes, int h)
{
    int gw = (blockIdx.x * blockDim.x + threadIdx.x) >> 5;
    int lane = threadIdx.x & 31;
    int ET = E + n_nodes;
    int e0 = gw * 2, e1 = gw * 2 + 1;
    if (e0 >= ET) return;

    int s0, d0;
    if (e0 < E) { s0 = ei[e0]; d0 = ei[(size_t)E + e0]; }
    else        { s0 = d0 = e0 - E; }
    bool v0 = (unsigned)s0 < (unsigned)n_nodes && (unsigned)d0 < (unsigned)n_nodes;

    int s1 = 0, d1 = 0;
    bool v1 = e1 < ET;
    if (v1) {
        if (e1 < E) { s1 = ei[e1]; d1 = ei[(size_t)E + e1]; }
        else        { s1 = d1 = e1 - E; }
        v1 = (unsigned)s1 < (unsigned)n_nodes && (unsigned)d1 < (unsigned)n_nodes;
    }

    const float4* attp = (const float4*)(att + h * D_DIM);
    float4 at = attp[lane];

    float4 a0 = make_float4(0.f,0.f,0.f,0.f), b0 = a0, a1 = a0, b1 = a0;
    if (v0) {
        a0 = ((const float4*)(g_xl + (size_t)s0 * HD + h * D_DIM))[lane];
        b0 = ((const float4*)(g_xr + (size_t)d0 * HD + h * D_DIM))[lane];
    }
    if (v1) {
        a1 = ((const float4*)(g_xl + (size_t)s1 * HD + h * D_DIM))[lane];
        b1 = ((const float4*)(g_xr + (size_t)d1 * HD + h * D_DIM))[lane];
    }

    float ex, ey, ez, ew;
    ex = a0.x + b0.x; ey = a0.y + b0.y; ez = a0.z + b0.z; ew = a0.w + b0.w;
    ex = ex > 0.f ? ex : NEG_SLOPE * ex;
    ey = ey > 0.f ? ey : NEG_SLOPE * ey;
    ez = ez > 0.f ? ez : NEG_SLOPE * ez;
    ew = ew > 0.f ? ew : NEG_SLOPE * ew;
    float dot0 = ex * at.x + ey * at.y + ez * at.z + ew * at.w;

    ex = a1.x + b1.x; ey = a1.y + b1.y; ez = a1.z + b1.z; ew = a1.w + b1.w;
    ex = ex > 0.f ? ex : NEG_SLOPE * ex;
    ey = ey > 0.f ? ey : NEG_SLOPE * ey;
    ez = ez > 0.f ? ez : NEG_SLOPE * ez;
    ew = ew > 0.f ? ew : NEG_SLOPE * ew;
    float dot1 = ex * at.x + ey * at.y + ez * at.z + ew * at.w;

#pragma unroll
    for (int o = 16; o > 0; o >>= 1) {
        dot0 += __shfl_xor_sync(0xffffffffu, dot0, o);
        dot1 += __shfl_xor_sync(0xffffffffu, dot1, o);
    }
    float p0 = __expf(dot0);
    float p1 = __expf(dot1);

    if (lane == 0 && v0) atomicAdd(&g_denom[(size_t)d0 * 2 + h], p0);
    if (lane == 1 && v1) atomicAdd(&g_denom[(size_t)d1 * 2 + h], p1);

    if (v0) {
        float* np = g_numer + (size_t)d0 * HD + h * D_DIM;
        red_add_v4(np + lane * 4, a0.x * p0, a0.y * p0, a0.z * p0, a0.w * p0);
    }
    if (v1) {
        float* np = g_numer + (size_t)d1 * HD + h * D_DIM;
        red_add_v4(np + lane * 4, a1.x * p1, a1.y * p1, a1.z * p1, a1.w * p1);
    }
}

// ---------------- launch ----------------
extern "C" void kernel_launch(void* const* d_in, const int* in_sizes, int n_in,
                              void* d_out, int out_size)
{
    const float* x         = (const float*)d_in[0];
    const int*   ei        = (const int*)d_in[1];     // int32 (JAX x64-disabled)
    const float* Wl        = (const float*)d_in[2];
    const float* bl        = (const float*)d_in[3];
    const float* Wr        = (const float*)d_in[4];
    const float* br        = (const float*)d_in[5];
    const float* att       = (const float*)d_in[6];
    const float* bias_conv = (const float*)d_in[7];
    const float* Wo        = (const float*)d_in[8];
    const float* bo        = (const float*)d_in[9];

    int N = in_sizes[0] / D_DIM;
    int E = in_sizes[1] / 2;
    int ET = E + N;

    // init: zero numer/denom + pre-round x and weights to tf32
    {
        int t = N * 96 + 24576;
        init_kernel<<<(t + 255) / 256, 256>>>(x, Wl, Wr, Wo, N);
    }
    // fused projections: xl = x@Wl^T+bl, xr = x@Wr^T+br in one launch
    {
        dim3 grid(4, (N + BM - 1) / BM);
        gemm_tf32<<<grid, 256>>>(bl, br, nullptr, nullptr, 0, N, D_DIM);
    }
    // edge passes: one per head, 2 edges per warp
    {
        int warps = (ET + 1) / 2;
        int blocks = (warps + 7) / 8;
        edge_head_kernel<<<blocks, 256>>>(ei, att, E, N, 0);
        edge_head_kernel<<<blocks, 256>>>(ei, att, E, N, 1);
    }
    // final projection with fused normalize: out = (numer/denom + bias_conv)@Wo^T + bo
    {
        dim3 grid(1, (N + BM - 1) / BM);
        gemm_tf32<<<grid, 256>>>(bo, nullptr, bias_conv, (float*)d_out, 1, N, HD);
    }
}

// round 13
// speedup vs baseline: 1.4180x; 1.4180x over previous
#include <cuda_runtime.h>
#include <cuda_bf16.h>
#include <cuda_fp16.h>
#include <mma.h>
#include <cstdint>

using namespace nvcuda;

// Problem constants (fixed by the dataset)
#define MAXN 50000
#define MAXE 400000
#define HD 256          // H * D
#define D_DIM 128
#define NEG_SLOPE 0.2f

// ---------------- scratch (no allocations allowed) ----------------
__device__ float  g_xl[(size_t)MAXN * HD];      // source projection  [N,256]
__device__ float  g_xr[(size_t)MAXN * HD];      // target projection  [N,256]
__device__ float  g_numer[(size_t)MAXN * HD];   // weighted sums (un-normalized)
__device__ float  g_denom[(size_t)MAXN * 2];    // sum of exp(score) per node/head
__device__ __half g_xh[(size_t)MAXN * D_DIM];   // x in fp16
__device__ __half g_wh[3 * HD * D_DIM];         // Wl, Wr, Wo in fp16

__device__ __forceinline__ void red_add_v4(float* p, float a, float b, float c, float d) {
    asm volatile("red.global.add.v4.f32 [%0], {%1,%2,%3,%4};"
                 :: "l"(p), "f"(a), "f"(b), "f"(c), "f"(d) : "memory");
}
__device__ __forceinline__ uint4 f32x8_to_h8(float4 a, float4 b) {
    __half2 h0 = __floats2half2_rn(a.x, a.y);
    __half2 h1 = __floats2half2_rn(a.z, a.w);
    __half2 h2 = __floats2half2_rn(b.x, b.y);
    __half2 h3 = __floats2half2_rn(b.z, b.w);
    uint4 u;
    u.x = *(uint32_t*)&h0; u.y = *(uint32_t*)&h1;
    u.z = *(uint32_t*)&h2; u.w = *(uint32_t*)&h3;
    return u;
}

// ---------------- init: zero numer/denom + convert x, Wl, Wr, Wo to fp16 ----------------
// thread space: [0, N*64)            -> zero numer (float4)
//               [N*64, N*80)         -> convert x (8 floats each)
//               [N*80, N*80+12288)   -> convert Wl|Wr|Wo (8 floats each; 98304 floats total)
__global__ void init_kernel(const float* __restrict__ x,
                            const float* __restrict__ Wl,
                            const float* __restrict__ Wr,
                            const float* __restrict__ Wo, int n_nodes) {
    int i = blockIdx.x * blockDim.x + threadIdx.x;
    int t0 = n_nodes * 64;
    int t1 = t0 + n_nodes * 16;
    if (i < t0) {
        ((float4*)g_numer)[i] = make_float4(0.f, 0.f, 0.f, 0.f);
    } else if (i < t1) {
        int j = i - t0;                       // 8-float chunk of x
        const float4* src = (const float4*)x + (size_t)j * 2;
        ((uint4*)g_xh)[j] = f32x8_to_h8(src[0], src[1]);
    } else if (i < t1 + 12288) {
        int j = i - t1;                       // 8-float chunk; 4096 chunks per matrix
        const float* src = (j < 4096) ? Wl : (j < 8192) ? Wr : Wo;
        int jj = j & 4095;
        const float4* s4 = (const float4*)src + (size_t)jj * 2;
        ((uint4*)g_wh)[j] = f32x8_to_h8(s4[0], s4[1]);
    }
    if (i < n_nodes * 2) g_denom[i] = 0.f;
}

// ---------------- fp16 wmma GEMM (8 warps, 64x32 warp tiles) ----------------
// mode 0: A = g_xh [M,128], grid.x = 4 covers 512 output cols:
//         bn<256 -> Wl/bl -> g_xl col (bn&255);  bn>=256 -> Wr/br -> g_xr col (bn&255)
// mode 1: A = g_numer [M,256] normalized on stage (/denom + bias_conv) -> fp16,
//         W = g_wh + 2*HD*D_DIM (Wo), bias = biasa (=bo), C = Cparam [M,128]
#define BM 128
#define BN 128
#define BK 32
#define BKP 40          // padded smem stride in halves (80B rows, 16B aligned)

__global__ __launch_bounds__(256, 2) void gemm_f16(
    const float* __restrict__ biasa, const float* __restrict__ biasb,
    const float* __restrict__ bias_conv,
    float* __restrict__ Cparam, int mode, int M, int K)
{
    __shared__ __half As[BM][BKP];
    __shared__ __half Bs[BM][BKP];

    int tid  = threadIdx.x;
    int wid  = tid >> 5;
    int lane = tid & 31;
    int bm = blockIdx.y * BM;
    int bn = blockIdx.x * BN;

    const __half* Wh;
    const float*  bias;
    float* C;
    int Ncol, cbase;
    if (mode == 0) {
        bool second = bn >= 256;
        int wrow = bn & 255;
        Wh   = g_wh + (second ? (HD * D_DIM) : 0) + (size_t)wrow * K;
        bias = (second ? biasb : biasa) + wrow;
        C    = second ? g_xr : g_xl;
        Ncol = HD; cbase = wrow;
    } else {
        Wh   = g_wh + 2 * HD * D_DIM;
        bias = biasa;
        C = Cparam; Ncol = D_DIM; cbase = 0;
    }

    // warp tiling: 2 warps along M (64 rows), 4 along N (32 cols)
    int wm = (wid & 1) * 64;
    int wn = (wid >> 1) * 32;

    // ---- bias -> accumulator init (staged in As/Bs region: 16x128 floats = 8KB < 20KB) ----
    float* bias_s = (float*)&As[0][0];
    for (int i = tid; i < 16 * BN; i += 256) bias_s[i] = bias[i & 127];
    __syncthreads();

    wmma::fragment<wmma::accumulator, 16, 16, 16, float> acc[4][2];
#pragma unroll
    for (int i = 0; i < 4; i++)
#pragma unroll
        for (int j = 0; j < 2; j++)
            wmma::load_matrix_sync(acc[i][j], bias_s + wn + j * 16, BN, wmma::mem_row_major);
    __syncthreads();

    for (int k0 = 0; k0 < K; k0 += BK) {
        int head = (k0 >= D_DIM) ? 1 : 0;       // used only in mode 1 (K=256)
        // stage A tile 128x32 halves: idx in [0,512): row=idx>>2, q=idx&3 (8-half slot)
#pragma unroll
        for (int it = 0; it < 2; it++) {
            int idx = tid + it * 256;
            int row = idx >> 2;
            int q   = idx & 3;
            int grow = bm + row;
            uint4 u = make_uint4(0u, 0u, 0u, 0u);
            if (grow < M) {
                if (mode == 0) {
                    u = *(const uint4*)(g_xh + (size_t)grow * K + k0 + q * 8);
                } else {
                    const float* ap = g_numer + (size_t)grow * K + k0 + q * 8;
                    float4 a = *(const float4*)(ap);
                    float4 b = *(const float4*)(ap + 4);
                    float inv = 1.0f / (g_denom[(size_t)grow * 2 + head] + 1e-16f);
                    const float* bc = bias_conv + k0 + q * 8;
                    float4 c0 = *(const float4*)(bc);
                    float4 c1 = *(const float4*)(bc + 4);
                    a.x = a.x * inv + c0.x; a.y = a.y * inv + c0.y;
                    a.z = a.z * inv + c0.z; a.w = a.w * inv + c0.w;
                    b.x = b.x * inv + c1.x; b.y = b.y * inv + c1.y;
                    b.z = b.z * inv + c1.z; b.w = b.w * inv + c1.w;
                    u = f32x8_to_h8(a, b);
                }
            }
            *(uint4*)&As[row][q * 8] = u;
            // W tile 128x32 halves (local rows 0..127)
            uint4 w = *(const uint4*)(Wh + (size_t)row * K + k0 + q * 8);
            *(uint4*)&Bs[row][q * 8] = w;
        }
        __syncthreads();

#pragma unroll
        for (int kk = 0; kk < BK; kk += 16) {
            wmma::fragment<wmma::matrix_a, 16, 16, 16, __half, wmma::row_major> af[4];
            wmma::fragment<wmma::matrix_b, 16, 16, 16, __half, wmma::col_major> bf[2];
#pragma unroll
            for (int i = 0; i < 4; i++)
                wmma::load_matrix_sync(af[i], &As[wm + i * 16][kk], BKP);
#pragma unroll
            for (int j = 0; j < 2; j++)
                wmma::load_matrix_sync(bf[j], &Bs[wn + j * 16][kk], BKP);
#pragma unroll
            for (int i = 0; i < 4; i++)
#pragma unroll
                for (int j = 0; j < 2; j++)
                    wmma::mma_sync(acc[i][j], af[i], bf[j], acc[i][j]);
        }
        __syncthreads();
    }

    // epilogue
    if (bm + BM <= M) {
#pragma unroll
        for (int i = 0; i < 4; i++)
#pragma unroll
            for (int j = 0; j < 2; j++)
                wmma::store_matrix_sync(C + (size_t)(bm + wm + i * 16) * Ncol + cbase + wn + j * 16,
                                        acc[i][j], Ncol, wmma::mem_row_major);
    } else {
        // remainder block: stage each 16x16 fragment in per-warp smem, guarded writes
        float* sw = (float*)&As[0][0] + wid * (16 * 20);   // 8 warps x 1280B = 10KB < 20KB
#pragma unroll
        for (int i = 0; i < 4; i++)
#pragma unroll
            for (int j = 0; j < 2; j++) {
                wmma::store_matrix_sync(sw, acc[i][j], 20, wmma::mem_row_major);
                __syncwarp();
                int r  = lane >> 1;
                int c0 = (lane & 1) * 8;
                int grow = bm + wm + i * 16 + r;
                if (grow < M) {
                    float* dst = C + (size_t)grow * Ncol + cbase + wn + j * 16 + c0;
#pragma unroll
                    for (int c = 0; c < 8; c++) dst[c] = sw[r * 20 + c0 + c];
                }
                __syncwarp();
            }
    }
}

// ---------------- edge pass, one head per launch, 2 edges per warp (unchanged) ----------------
__global__ __launch_bounds__(256) void edge_head_kernel(
    const int* __restrict__ ei, const float* __restrict__ att,
    int E, int n_nodes, int h)
{
    int gw = (blockIdx.x * blockDim.x + threadIdx.x) >> 5;
    int lane = threadIdx.x & 31;
    int ET = E + n_nodes;
    int e0 = gw * 2, e1 = gw * 2 + 1;
    if (e0 >= ET) return;

    int s0, d0;
    if (e0 < E) { s0 = ei[e0]; d0 = ei[(size_t)E + e0]; }
    else        { s0 = d0 = e0 - E; }
    bool v0 = (unsigned)s0 < (unsigned)n_nodes && (unsigned)d0 < (unsigned)n_nodes;

    int s1 = 0, d1 = 0;
    bool v1 = e1 < ET;
    if (v1) {
        if (e1 < E) { s1 = ei[e1]; d1 = ei[(size_t)E + e1]; }
        else        { s1 = d1 = e1 - E; }
        v1 = (unsigned)s1 < (unsigned)n_nodes && (unsigned)d1 < (unsigned)n_nodes;
    }

    const float4* attp = (const float4*)(att + h * D_DIM);
    float4 at = attp[lane];

    float4 a0 = make_float4(0.f,0.f,0.f,0.f), b0 = a0, a1 = a0, b1 = a0;
    if (v0) {
        a0 = ((const float4*)(g_xl + (size_t)s0 * HD + h * D_DIM))[lane];
        b0 = ((const float4*)(g_xr + (size_t)d0 * HD + h * D_DIM))[lane];
    }
    if (v1) {
        a1 = ((const float4*)(g_xl + (size_t)s1 * HD + h * D_DIM))[lane];
        b1 = ((const float4*)(g_xr + (size_t)d1 * HD + h * D_DIM))[lane];
    }

    float ex, ey, ez, ew;
    ex = a0.x + b0.x; ey = a0.y + b0.y; ez = a0.z + b0.z; ew = a0.w + b0.w;
    ex = ex > 0.f ? ex : NEG_SLOPE * ex;
    ey = ey > 0.f ? ey : NEG_SLOPE * ey;
    ez = ez > 0.f ? ez : NEG_SLOPE * ez;
    ew = ew > 0.f ? ew : NEG_SLOPE * ew;
    float dot0 = ex * at.x + ey * at.y + ez * at.z + ew * at.w;

    ex = a1.x + b1.x; ey = a1.y + b1.y; ez = a1.z + b1.z; ew = a1.w + b1.w;
    ex = ex > 0.f ? ex : NEG_SLOPE * ex;
    ey = ey > 0.f ? ey : NEG_SLOPE * ey;
    ez = ez > 0.f ? ez : NEG_SLOPE * ez;
    ew = ew > 0.f ? ew : NEG_SLOPE * ew;
    float dot1 = ex * at.x + ey * at.y + ez * at.z + ew * at.w;

#pragma unroll
    for (int o = 16; o > 0; o >>= 1) {
        dot0 += __shfl_xor_sync(0xffffffffu, dot0, o);
        dot1 += __shfl_xor_sync(0xffffffffu, dot1, o);
    }
    float p0 = __expf(dot0);
    float p1 = __expf(dot1);

    if (lane == 0 && v0) atomicAdd(&g_denom[(size_t)d0 * 2 + h], p0);
    if (lane == 1 && v1) atomicAdd(&g_denom[(size_t)d1 * 2 + h], p1);

    if (v0) {
        float* np = g_numer + (size_t)d0 * HD + h * D_DIM;
        red_add_v4(np + lane * 4, a0.x * p0, a0.y * p0, a0.z * p0, a0.w * p0);
    }
    if (v1) {
        float* np = g_numer + (size_t)d1 * HD + h * D_DIM;
        red_add_v4(np + lane * 4, a1.x * p1, a1.y * p1, a1.z * p1, a1.w * p1);
    }
}

// ---------------- launch ----------------
extern "C" void kernel_launch(void* const* d_in, const int* in_sizes, int n_in,
                              void* d_out, int out_size)
{
    const float* x         = (const float*)d_in[0];
    const int*   ei        = (const int*)d_in[1];     // int32 (JAX x64-disabled)
    const float* Wl        = (const float*)d_in[2];
    const float* bl        = (const float*)d_in[3];
    const float* Wr        = (const float*)d_in[4];
    const float* br        = (const float*)d_in[5];
    const float* att       = (const float*)d_in[6];
    const float* bias_conv = (const float*)d_in[7];
    const float* Wo        = (const float*)d_in[8];
    const float* bo        = (const float*)d_in[9];

    int N = in_sizes[0] / D_DIM;
    int E = in_sizes[1] / 2;
    int ET = E + N;
    int mtiles = (N + BM - 1) / BM;

    // init: zero numer/denom + convert x and weights to fp16
    {
        int t = N * 80 + 12288;
        init_kernel<<<(t + 255) / 256, 256>>>(x, Wl, Wr, Wo, N);
    }
    // fused projections: xl = x@Wl^T+bl, xr = x@Wr^T+br  (fp16 wmma)
    {
        dim3 grid(4, mtiles);
        gemm_f16<<<grid, 256>>>(bl, br, nullptr, nullptr, 0, N, D_DIM);
    }
    // edge passes: one per head, 2 edges per warp
    {
        int warps = (ET + 1) / 2;
        int blocks = (warps + 7) / 8;
        edge_head_kernel<<<blocks, 256>>>(ei, att, E, N, 0);
        edge_head_kernel<<<blocks, 256>>>(ei, att, E, N, 1);
    }
    // final projection with fused normalize: out = (numer/denom + bias_conv)@Wo^T + bo
    {
        dim3 grid(1, mtiles);
        gemm_f16<<<grid, 256>>>(bo, nullptr, bias_conv, (float*)d_out, 1, N, HD);
    }
}